// round 1
// baseline (speedup 1.0000x reference)
#include <cuda_runtime.h>
#include <cuda_bf16.h>
#include <math.h>

#define MAXN 100000
#define MAXE 1600000
#define H 64
#define H2 128

// ---------------- scratch (static device globals; no allocs) ----------------
__device__ float d_bufA[MAXN * H];   // agg output (both layers)
__device__ float d_bufB[MAXN * H];   // h1
__device__ float d_bufC[MAXN * H];   // g = relu(ln(h1))  /  h0 (encoder out)
__device__ float d_bufD[MAXN * H];   // h2
__device__ float d_bufE[MAXN * H];   // h0
__device__ int   d_off[MAXN + 1];    // degree -> offsets (in place scan)
__device__ int   d_cur[MAXN];        // scatter cursors
__device__ int   d_adj[MAXE];        // src ids sorted by dst
__device__ int   d_bsum[1024];       // scan block sums

// ---------------- encoder: h = x @ W_enc + b_enc  ([N,16]@[16,64]) ----------
__global__ void k_encoder(const float* __restrict__ x, const float* __restrict__ W,
                          const float* __restrict__ b, float* __restrict__ h, int N) {
    __shared__ float Ws[16 * H];
    __shared__ float bs[H];
    for (int i = threadIdx.x; i < 16 * H; i += blockDim.x) Ws[i] = W[i];
    if (threadIdx.x < H) bs[threadIdx.x] = b[threadIdx.x];
    __syncthreads();
    int total = N * H;
    for (int idx = blockIdx.x * blockDim.x + threadIdx.x; idx < total;
         idx += gridDim.x * blockDim.x) {
        int n = idx >> 6, j = idx & 63;
        const float* xr = x + n * 16;
        float a0 = bs[j], a1 = 0.f, a2 = 0.f, a3 = 0.f;
        #pragma unroll
        for (int k = 0; k < 16; k += 4) {
            a0 += xr[k]     * Ws[k * H + j];
            a1 += xr[k + 1] * Ws[(k + 1) * H + j];
            a2 += xr[k + 2] * Ws[(k + 2) * H + j];
            a3 += xr[k + 3] * Ws[(k + 3) * H + j];
        }
        h[idx] = (a0 + a1) + (a2 + a3);
    }
}

// ---------------- CSR build ----------------
__global__ void k_zero_int(int* __restrict__ a, int n) {
    for (int i = blockIdx.x * blockDim.x + threadIdx.x; i < n; i += gridDim.x * blockDim.x)
        a[i] = 0;
}

__global__ void k_count(const int* __restrict__ dst, int* __restrict__ deg, int E) {
    for (int e = blockIdx.x * blockDim.x + threadIdx.x; e < E; e += gridDim.x * blockDim.x)
        atomicAdd(&deg[dst[e]], 1);
}

__global__ void k_scan1(int* __restrict__ data, int* __restrict__ bsum, int N) {
    __shared__ int s[1024];
    int i = blockIdx.x * 1024 + threadIdx.x;
    int v = (i < N) ? data[i] : 0;
    s[threadIdx.x] = v;
    __syncthreads();
    for (int off = 1; off < 1024; off <<= 1) {
        int t = (threadIdx.x >= off) ? s[threadIdx.x - off] : 0;
        __syncthreads();
        s[threadIdx.x] += t;
        __syncthreads();
    }
    if (i < N) data[i] = s[threadIdx.x] - v;   // exclusive
    if (threadIdx.x == 1023) bsum[blockIdx.x] = s[1023];
}

__global__ void k_scan2(int* __restrict__ bsum, int nb) {
    if (blockIdx.x == 0 && threadIdx.x == 0) {
        int run = 0;
        for (int b = 0; b < nb; b++) { int t = bsum[b]; bsum[b] = run; run += t; }
    }
}

__global__ void k_scan3(int* __restrict__ off, int* __restrict__ cur,
                        const int* __restrict__ bsum, int N, int E) {
    int i = blockIdx.x * blockDim.x + threadIdx.x;
    if (i < N) {
        int o = off[i] + bsum[i >> 10];
        off[i] = o;
        cur[i] = o;
    }
    if (i == 0) off[N] = E;
}

__global__ void k_scatter(const int* __restrict__ src, const int* __restrict__ dst,
                          int* __restrict__ cur, int* __restrict__ adj, int E) {
    for (int e = blockIdx.x * blockDim.x + threadIdx.x; e < E; e += gridDim.x * blockDim.x) {
        int p = atomicAdd(&cur[dst[e]], 1);
        adj[p] = src[e];
    }
}

// ---------------- GENConv softmax aggregation (max-free, CSR) ----------------
// out[n] = sum_j msg_j * exp(t*msg_j) / (sum_j exp(t*msg_j) + 1e-16) + feat[n]
// msg_j = relu(feat[adj[j]]) + 1e-7
__global__ void k_agg(const float* __restrict__ feat, float* __restrict__ out,
                      const int* __restrict__ off, const int* __restrict__ adj,
                      const float* __restrict__ tptr, int N) {
    int gid = blockIdx.x * (blockDim.x >> 6) + (threadIdx.x >> 6);
    int f = threadIdx.x & 63;
    if (gid >= N) return;
    float t = tptr[0];
    int beg = off[gid], end = off[gid + 1];
    float num = 0.f, den = 0.f;
    for (int j = beg; j < end; j++) {
        int s = adj[j];
        float v = feat[s * H + f];
        v = fmaxf(v, 0.f) + 1e-7f;
        float w = __expf(v * t);
        num += v * w;
        den += w;
    }
    out[gid * H + f] = num / (den + 1e-16f) + feat[gid * H + f];
}

// ---------------- MLP: relu(LN(in@W1+b1; g1,be1)) @ W2 + b2 (+res) ----------
__global__ void k_mlp(const float* __restrict__ in, float* __restrict__ out,
                      const float* __restrict__ res,
                      const float* __restrict__ W1, const float* __restrict__ b1,
                      const float* __restrict__ g1, const float* __restrict__ be1,
                      const float* __restrict__ W2, const float* __restrict__ b2, int N) {
    extern __shared__ float sm[];
    float* sW1  = sm;                 // 64*128
    float* sW2  = sW1 + H * H2;       // 128*64
    float* sb1  = sW2 + H2 * H;       // 128
    float* sg1  = sb1 + H2;           // 128
    float* sbe1 = sg1 + H2;           // 128
    float* sb2  = sbe1 + H2;          // 64
    float* sin  = sb2 + H;            // 2*64
    float* shid = sin + 2 * H;        // 2*128
    float* srs  = shid + 2 * H2;      // 2*128
    float* srq  = srs + 2 * H2;       // 2*128

    int tid = threadIdx.x;
    for (int i = tid; i < H * H2; i += 256) sW1[i] = W1[i];
    for (int i = tid; i < H2 * H; i += 256) sW2[i] = W2[i];
    if (tid < H2) { sb1[tid] = b1[tid]; sg1[tid] = g1[tid]; sbe1[tid] = be1[tid]; }
    if (tid < H) sb2[tid] = b2[tid];
    __syncthreads();

    int grp = tid >> 7;           // 0/1
    int j = tid & 127;
    float* gin  = sin + grp * H;
    float* ghid = shid + grp * H2;
    float* grs  = srs + grp * H2;
    float* grq  = srq + grp * H2;

    for (int n0 = blockIdx.x * 2; n0 < N; n0 += gridDim.x * 2) {
        int n = n0 + grp;
        bool valid = (n < N);
        int nc = valid ? n : (N - 1);
        if (j < H) gin[j] = in[nc * H + j];
        __syncthreads();

        float a0 = 0.f, a1 = 0.f, a2 = 0.f, a3 = 0.f;
        #pragma unroll
        for (int k = 0; k < H; k += 4) {
            a0 += gin[k]     * sW1[k * H2 + j];
            a1 += gin[k + 1] * sW1[(k + 1) * H2 + j];
            a2 += gin[k + 2] * sW1[(k + 2) * H2 + j];
            a3 += gin[k + 3] * sW1[(k + 3) * H2 + j];
        }
        float h = sb1[j] + (a0 + a1) + (a2 + a3);

        grs[j] = h;
        grq[j] = h * h;
        __syncthreads();
        for (int s = 64; s > 0; s >>= 1) {
            if (j < s) { grs[j] += grs[j + s]; grq[j] += grq[j + s]; }
            __syncthreads();
        }
        float mu  = grs[0] * (1.f / 128.f);
        float var = grq[0] * (1.f / 128.f) - mu * mu;
        float y = (h - mu) * rsqrtf(var + 1e-5f) * sg1[j] + sbe1[j];
        ghid[j] = fmaxf(y, 0.f);
        __syncthreads();

        if (j < H && valid) {
            float c0 = 0.f, c1 = 0.f, c2 = 0.f, c3 = 0.f;
            #pragma unroll
            for (int k = 0; k < H2; k += 4) {
                c0 += ghid[k]     * sW2[k * H + j];
                c1 += ghid[k + 1] * sW2[(k + 1) * H + j];
                c2 += ghid[k + 2] * sW2[(k + 2) * H + j];
                c3 += ghid[k + 3] * sW2[(k + 3) * H + j];
            }
            float o = sb2[j] + (c0 + c1) + (c2 + c3);
            if (res) o += res[n * H + j];
            out[n * H + j] = o;
        }
        __syncthreads();
    }
}

// ---------------- LN(64) + ReLU, warp per node ----------------
__global__ void k_ln64_relu(const float* __restrict__ in, float* __restrict__ out,
                            const float* __restrict__ g, const float* __restrict__ b, int N) {
    int warp = (blockIdx.x * blockDim.x + threadIdx.x) >> 5;
    int lane = threadIdx.x & 31;
    if (warp >= N) return;
    float v1 = in[warp * H + lane];
    float v2 = in[warp * H + lane + 32];
    float s = v1 + v2, q = v1 * v1 + v2 * v2;
    #pragma unroll
    for (int o = 16; o; o >>= 1) {
        s += __shfl_xor_sync(0xffffffffu, s, o);
        q += __shfl_xor_sync(0xffffffffu, q, o);
    }
    float mu = s * (1.f / 64.f);
    float var = q * (1.f / 64.f) - mu * mu;
    float inv = rsqrtf(var + 1e-5f);
    out[warp * H + lane]      = fmaxf((v1 - mu) * inv * g[lane] + b[lane], 0.f);
    out[warp * H + lane + 32] = fmaxf((v2 - mu) * inv * g[lane + 32] + b[lane + 32], 0.f);
}

// ---------------- final: relu(LN(h)) @ W_lin + b_lin -> sigmoid,logits ------
__global__ void k_final(const float* __restrict__ h, const float* __restrict__ g,
                        const float* __restrict__ b, const float* __restrict__ Wl,
                        const float* __restrict__ bl, float* __restrict__ out, int N) {
    int warp = (blockIdx.x * blockDim.x + threadIdx.x) >> 5;
    int lane = threadIdx.x & 31;
    if (warp >= N) return;
    float v1 = h[warp * H + lane];
    float v2 = h[warp * H + lane + 32];
    float s = v1 + v2, q = v1 * v1 + v2 * v2;
    #pragma unroll
    for (int o = 16; o; o >>= 1) {
        s += __shfl_xor_sync(0xffffffffu, s, o);
        q += __shfl_xor_sync(0xffffffffu, q, o);
    }
    float mu = s * (1.f / 64.f);
    float var = q * (1.f / 64.f) - mu * mu;
    float inv = rsqrtf(var + 1e-5f);
    float y1 = fmaxf((v1 - mu) * inv * g[lane] + b[lane], 0.f);
    float y2 = fmaxf((v2 - mu) * inv * g[lane + 32] + b[lane + 32], 0.f);
    float p = y1 * Wl[lane] + y2 * Wl[lane + 32];
    #pragma unroll
    for (int o = 16; o; o >>= 1) p += __shfl_xor_sync(0xffffffffu, p, o);
    if (lane == 0) {
        float logit = p + bl[0];
        out[warp]     = 1.f / (1.f + expf(-logit));
        out[N + warp] = logit;
    }
}

// ---------------- host launcher ----------------
extern "C" void kernel_launch(void* const* d_in, const int* in_sizes, int n_in,
                              void* d_out, int out_size) {
    const float* x      = (const float*)d_in[0];
    const int*   eidx   = (const int*)d_in[1];
    const float* W_enc  = (const float*)d_in[2];
    const float* b_enc  = (const float*)d_in[3];
    const float* t1     = (const float*)d_in[4];
    const float* W1a    = (const float*)d_in[5];
    const float* b1a    = (const float*)d_in[6];
    const float* g1a    = (const float*)d_in[7];
    const float* be1a   = (const float*)d_in[8];
    const float* W1b    = (const float*)d_in[9];
    const float* b1b    = (const float*)d_in[10];
    const float* g_n1   = (const float*)d_in[11];
    const float* b_n1   = (const float*)d_in[12];
    const float* t2     = (const float*)d_in[13];
    const float* W2a    = (const float*)d_in[14];
    const float* b2a    = (const float*)d_in[15];
    const float* g2a    = (const float*)d_in[16];
    const float* be2a   = (const float*)d_in[17];
    const float* W2b    = (const float*)d_in[18];
    const float* b2b    = (const float*)d_in[19];
    const float* g_n0   = (const float*)d_in[20];
    const float* b_n0   = (const float*)d_in[21];
    const float* W_lin  = (const float*)d_in[22];
    const float* b_lin  = (const float*)d_in[23];
    float* out = (float*)d_out;

    int N = in_sizes[0] / 16;
    int E = in_sizes[1] / 2;
    if (N > MAXN) N = MAXN;
    if (E > MAXE) E = MAXE;
    const int* src = eidx;
    const int* dst = eidx + E;

    float *pA, *pB, *pC, *pD, *pE;
    int *pOff, *pCur, *pAdj, *pBsum;
    cudaGetSymbolAddress((void**)&pA, d_bufA);
    cudaGetSymbolAddress((void**)&pB, d_bufB);
    cudaGetSymbolAddress((void**)&pC, d_bufC);
    cudaGetSymbolAddress((void**)&pD, d_bufD);
    cudaGetSymbolAddress((void**)&pE, d_bufE);
    cudaGetSymbolAddress((void**)&pOff, d_off);
    cudaGetSymbolAddress((void**)&pCur, d_cur);
    cudaGetSymbolAddress((void**)&pAdj, d_adj);
    cudaGetSymbolAddress((void**)&pBsum, d_bsum);

    static bool attr_done = false;
    const int mlp_smem = (H * H2 + H2 * H + 3 * H2 + H + 2 * H + 6 * H2) * (int)sizeof(float);
    if (!attr_done) {
        cudaFuncSetAttribute(k_mlp, cudaFuncAttributeMaxDynamicSharedMemorySize, mlp_smem);
        attr_done = true;
    }

    int nb_scan = (N + 1023) / 1024;

    // encoder -> h0 (bufE)
    k_encoder<<<(N * H + 255) / 256, 256>>>(x, W_enc, b_enc, pE, N);

    // CSR build (per launch; deterministic work)
    k_zero_int<<<(N + 255) / 256, 256>>>(pOff, N);
    k_count<<<(E + 255) / 256, 256>>>(dst, pOff, E);
    k_scan1<<<nb_scan, 1024>>>(pOff, pBsum, N);
    k_scan2<<<1, 32>>>(pBsum, nb_scan);
    k_scan3<<<nb_scan, 1024>>>(pOff, pCur, pBsum, N, E);
    k_scatter<<<(E + 255) / 256, 256>>>(src, dst, pCur, pAdj, E);

    // layer 1: agg(h0) -> bufA ; MLP1 -> h1 (bufB)
    k_agg<<<(N + 3) / 4, 256>>>(pE, pA, pOff, pAdj, t1, N);
    k_mlp<<<1184, 256, mlp_smem>>>(pA, pB, (const float*)nullptr,
                                   W1a, b1a, g1a, be1a, W1b, b1b, N);

    // layer 2: g = relu(LN(h1)) -> bufC ; agg(g) -> bufA ; MLP2 + h1 -> h2 (bufD)
    k_ln64_relu<<<(N + 7) / 8, 256>>>(pB, pC, g_n1, b_n1, N);
    k_agg<<<(N + 3) / 4, 256>>>(pC, pA, pOff, pAdj, t2, N);
    k_mlp<<<1184, 256, mlp_smem>>>(pA, pD, pB,
                                   W2a, b2a, g2a, be2a, W2b, b2b, N);

    // final head
    k_final<<<(N + 7) / 8, 256>>>(pD, g_n0, b_n0, W_lin, b_lin, out, N);
}

// round 2
// speedup vs baseline: 2.2360x; 2.2360x over previous
#include <cuda_runtime.h>
#include <cuda_bf16.h>
#include <math.h>

#define MAXN 100000
#define MAXE 1600000
#define H 64
#define H2 128

// ---------------- scratch (static device globals; no allocs) ----------------
__device__ float d_bufA[MAXN * H];   // agg output (both layers)
__device__ float d_bufB[MAXN * H];   // h1
__device__ float d_bufC[MAXN * H];   // g = relu(ln(h1))
__device__ float d_bufD[MAXN * H];   // h2
__device__ float d_bufE[MAXN * H];   // h0
__device__ int   d_off[MAXN + 1];
__device__ int   d_cur[MAXN];
__device__ int   d_adj[MAXE];
__device__ int   d_bsum[1024];

// packed fp32x2 helpers (sm_103a FFMA2 path)
#define PK(d, lo, hi)  asm("mov.b64 %0, {%1, %2};" : "=l"(d) : "f"(lo), "f"(hi))
#define UPK(lo, hi, s) asm("mov.b64 {%0, %1}, %2;" : "=f"(lo), "=f"(hi) : "l"(s))
#define FMA2(d, a, b, c) asm("fma.rn.f32x2 %0, %1, %2, %3;" : "=l"(d) : "l"(a), "l"(b), "l"(c))

// ---------------- encoder: h = x @ W_enc + b_enc ----------------------------
__global__ void k_encoder(const float* __restrict__ x, const float* __restrict__ W,
                          const float* __restrict__ b, float* __restrict__ h, int N) {
    __shared__ float Ws[16 * H];
    __shared__ float bs[H];
    for (int i = threadIdx.x; i < 16 * H; i += blockDim.x) Ws[i] = W[i];
    if (threadIdx.x < H) bs[threadIdx.x] = b[threadIdx.x];
    __syncthreads();
    int total = N * H;
    for (int idx = blockIdx.x * blockDim.x + threadIdx.x; idx < total;
         idx += gridDim.x * blockDim.x) {
        int n = idx >> 6, j = idx & 63;
        const float* xr = x + n * 16;
        float a0 = bs[j], a1 = 0.f, a2 = 0.f, a3 = 0.f;
        #pragma unroll
        for (int k = 0; k < 16; k += 4) {
            a0 += xr[k]     * Ws[k * H + j];
            a1 += xr[k + 1] * Ws[(k + 1) * H + j];
            a2 += xr[k + 2] * Ws[(k + 2) * H + j];
            a3 += xr[k + 3] * Ws[(k + 3) * H + j];
        }
        h[idx] = (a0 + a1) + (a2 + a3);
    }
}

// ---------------- CSR build ----------------
__global__ void k_zero_int(int* __restrict__ a, int n) {
    for (int i = blockIdx.x * blockDim.x + threadIdx.x; i < n; i += gridDim.x * blockDim.x)
        a[i] = 0;
}

__global__ void k_count(const int* __restrict__ dst, int* __restrict__ deg, int E) {
    for (int e = blockIdx.x * blockDim.x + threadIdx.x; e < E; e += gridDim.x * blockDim.x)
        atomicAdd(&deg[dst[e]], 1);
}

__global__ void k_scan1(int* __restrict__ data, int* __restrict__ bsum, int N) {
    __shared__ int s[1024];
    int i = blockIdx.x * 1024 + threadIdx.x;
    int v = (i < N) ? data[i] : 0;
    s[threadIdx.x] = v;
    __syncthreads();
    for (int off = 1; off < 1024; off <<= 1) {
        int t = (threadIdx.x >= off) ? s[threadIdx.x - off] : 0;
        __syncthreads();
        s[threadIdx.x] += t;
        __syncthreads();
    }
    if (i < N) data[i] = s[threadIdx.x] - v;   // exclusive
    if (threadIdx.x == 1023) bsum[blockIdx.x] = s[1023];
}

__global__ void k_scan2(int* __restrict__ bsum, int nb) {
    if (blockIdx.x == 0 && threadIdx.x == 0) {
        int run = 0;
        for (int b = 0; b < nb; b++) { int t = bsum[b]; bsum[b] = run; run += t; }
    }
}

__global__ void k_scan3(int* __restrict__ off, int* __restrict__ cur,
                        const int* __restrict__ bsum, int N, int E) {
    int i = blockIdx.x * blockDim.x + threadIdx.x;
    if (i < N) {
        int o = off[i] + bsum[i >> 10];
        off[i] = o;
        cur[i] = o;
    }
    if (i == 0) off[N] = E;
}

__global__ void k_scatter(const int* __restrict__ src, const int* __restrict__ dst,
                          int* __restrict__ cur, int* __restrict__ adj, int E) {
    for (int e = blockIdx.x * blockDim.x + threadIdx.x; e < E; e += gridDim.x * blockDim.x) {
        int p = atomicAdd(&cur[dst[e]], 1);
        adj[p] = src[e];
    }
}

// ---------------- GENConv softmax aggregation (max-free, CSR) ----------------
__global__ void k_agg(const float* __restrict__ feat, float* __restrict__ out,
                      const int* __restrict__ off, const int* __restrict__ adj,
                      const float* __restrict__ tptr, int N) {
    int gid = blockIdx.x * (blockDim.x >> 6) + (threadIdx.x >> 6);
    int f = threadIdx.x & 63;
    if (gid >= N) return;
    float t = __ldg(tptr);
    int beg = off[gid], end = off[gid + 1];
    float num0 = 0.f, den0 = 0.f, num1 = 0.f, den1 = 0.f;
    int j = beg;
    for (; j + 1 < end; j += 2) {
        int s0 = adj[j], s1 = adj[j + 1];
        float v0 = feat[s0 * H + f];
        float v1 = feat[s1 * H + f];
        v0 = fmaxf(v0, 0.f) + 1e-7f;
        v1 = fmaxf(v1, 0.f) + 1e-7f;
        float w0 = __expf(v0 * t);
        float w1 = __expf(v1 * t);
        num0 += v0 * w0; den0 += w0;
        num1 += v1 * w1; den1 += w1;
    }
    if (j < end) {
        int s0 = adj[j];
        float v0 = fmaxf(feat[s0 * H + f], 0.f) + 1e-7f;
        float w0 = __expf(v0 * t);
        num0 += v0 * w0; den0 += w0;
    }
    float num = num0 + num1, den = den0 + den1;
    out[gid * H + f] = num / (den + 1e-16f) + feat[gid * H + f];
}

// ---------------- fused MLP: relu(LN(in@W1+b1)) @ W2 + b2 (+res) ------------
// 128 nodes per block, 512 threads, register-tiled GEMMs with packed f32x2 FMA.
#define TM 128
#define HSTRIDE 132
__global__ void __launch_bounds__(512, 1)
k_mlp(const float* __restrict__ in, float* __restrict__ out,
      const float* __restrict__ res,
      const float* __restrict__ W1, const float* __restrict__ b1,
      const float* __restrict__ g1, const float* __restrict__ be1,
      const float* __restrict__ W2, const float* __restrict__ b2, int N) {
    extern __shared__ float sm[];
    float* sW1  = sm;                       // 8192
    float* sW2  = sW1 + 8192;               // 8192
    float* sIn  = sW2 + 8192;               // 64 x 128 = 8192 (transposed [k][m])
    float* sHid = sIn + 8192;               // 128 x 132 = 16896 ([j][m])
    float* sRs  = sHid + 128 * HSTRIDE;     // 16 x 128
    float* sRq  = sRs + 2048;               // 16 x 128
    float* sMu  = sRq + 2048;               // 128
    float* sInv = sMu + 128;                // 128
    float* sb1  = sInv + 128;               // 128
    float* sg1  = sb1 + 128;                // 128
    float* sbe1 = sg1 + 128;                // 128
    float* sb2  = sbe1 + 128;               // 64

    const int tid = threadIdx.x;
    const int mg  = tid & 31;    // 32 m-groups x 4 nodes
    const int jg  = tid >> 5;    // 16 j-groups

    // load weights/biases
    {
        const float4* W14 = (const float4*)W1;
        const float4* W24 = (const float4*)W2;
        float4* sW14 = (float4*)sW1;
        float4* sW24 = (float4*)sW2;
        #pragma unroll
        for (int i = 0; i < 4; i++) {
            sW14[tid + i * 512] = W14[tid + i * 512];
            sW24[tid + i * 512] = W24[tid + i * 512];
        }
        if (tid < 128) { sb1[tid] = b1[tid]; sg1[tid] = g1[tid]; sbe1[tid] = be1[tid]; }
        else if (tid < 192) sb2[tid - 128] = b2[tid - 128];
    }

    // load + transpose input tile: sIn[k][m]
    {
        int nl = tid & 127;
        int q  = tid >> 7;       // 0..3
        int n  = blockIdx.x * TM + nl;
        if (n >= N) n = N - 1;
        const float4* ip = (const float4*)(in + n * H);
        #pragma unroll
        for (int i = 0; i < 4; i++) {
            float4 v = ip[q * 4 + i];
            int k0 = (q * 4 + i) * 4;
            sIn[(k0 + 0) * TM + nl] = v.x;
            sIn[(k0 + 1) * TM + nl] = v.y;
            sIn[(k0 + 2) * TM + nl] = v.z;
            sIn[(k0 + 3) * TM + nl] = v.w;
        }
    }
    __syncthreads();

    // ---- GEMM1: [128 x 64] @ [64 x 128]; thread tile 4m x 8j (4 jpairs) ----
    unsigned long long acc[4][4];
    #pragma unroll
    for (int a = 0; a < 4; a++)
        #pragma unroll
        for (int bq = 0; bq < 4; bq++) acc[a][bq] = 0ull;

    const float4* sIn4 = (const float4*)sIn;
    const float4* sW14 = (const float4*)sW1;
    #pragma unroll 8
    for (int k = 0; k < 64; k++) {
        float4 a  = sIn4[k * 32 + mg];
        float4 w0 = sW14[k * 32 + (jg << 1)];
        float4 w1 = sW14[k * 32 + (jg << 1) + 1];
        unsigned long long pa0, pa1, pa2, pa3, q0, q1, q2, q3;
        PK(pa0, a.x, a.x); PK(pa1, a.y, a.y); PK(pa2, a.z, a.z); PK(pa3, a.w, a.w);
        PK(q0, w0.x, w0.y); PK(q1, w0.z, w0.w); PK(q2, w1.x, w1.y); PK(q3, w1.z, w1.w);
        FMA2(acc[0][0], pa0, q0, acc[0][0]); FMA2(acc[0][1], pa0, q1, acc[0][1]);
        FMA2(acc[0][2], pa0, q2, acc[0][2]); FMA2(acc[0][3], pa0, q3, acc[0][3]);
        FMA2(acc[1][0], pa1, q0, acc[1][0]); FMA2(acc[1][1], pa1, q1, acc[1][1]);
        FMA2(acc[1][2], pa1, q2, acc[1][2]); FMA2(acc[1][3], pa1, q3, acc[1][3]);
        FMA2(acc[2][0], pa2, q0, acc[2][0]); FMA2(acc[2][1], pa2, q1, acc[2][1]);
        FMA2(acc[2][2], pa2, q2, acc[2][2]); FMA2(acc[2][3], pa2, q3, acc[2][3]);
        FMA2(acc[3][0], pa3, q0, acc[3][0]); FMA2(acc[3][1], pa3, q1, acc[3][1]);
        FMA2(acc[3][2], pa3, q2, acc[3][2]); FMA2(acc[3][3], pa3, q3, acc[3][3]);
    }

    // bias + per-node partial LN sums
    float hreg[4][8];
    {
        float4 psum, psq;
        float* ps = (float*)&psum;
        float* pq = (float*)&psq;
        #pragma unroll
        for (int mi = 0; mi < 4; mi++) {
            float s = 0.f, q = 0.f;
            #pragma unroll
            for (int jp = 0; jp < 4; jp++) {
                float lo, hi;
                UPK(lo, hi, acc[mi][jp]);
                lo += sb1[(jg << 3) + 2 * jp];
                hi += sb1[(jg << 3) + 2 * jp + 1];
                hreg[mi][2 * jp] = lo; hreg[mi][2 * jp + 1] = hi;
                s += lo + hi; q += lo * lo + hi * hi;
            }
            ps[mi] = s; pq[mi] = q;
        }
        *(float4*)&sRs[jg * TM + (mg << 2)] = psum;
        *(float4*)&sRq[jg * TM + (mg << 2)] = psq;
    }
    __syncthreads();
    if (tid < TM) {
        float s = 0.f, q = 0.f;
        #pragma unroll
        for (int g = 0; g < 16; g++) { s += sRs[g * TM + tid]; q += sRq[g * TM + tid]; }
        float mu = s * (1.f / 128.f);
        float var = q * (1.f / 128.f) - mu * mu;
        sMu[tid] = mu;
        sInv[tid] = rsqrtf(var + 1e-5f);
    }
    __syncthreads();

    // LN + ReLU -> sHid[j][m] (float4 along m, conflict-free)
    {
        float mu[4], iv[4];
        #pragma unroll
        for (int mi = 0; mi < 4; mi++) { mu[mi] = sMu[(mg << 2) + mi]; iv[mi] = sInv[(mg << 2) + mi]; }
        #pragma unroll
        for (int jj = 0; jj < 8; jj++) {
            int j = (jg << 3) + jj;
            float gg = sg1[j], bb = sbe1[j];
            float4 v;
            v.x = fmaxf((hreg[0][jj] - mu[0]) * iv[0] * gg + bb, 0.f);
            v.y = fmaxf((hreg[1][jj] - mu[1]) * iv[1] * gg + bb, 0.f);
            v.z = fmaxf((hreg[2][jj] - mu[2]) * iv[2] * gg + bb, 0.f);
            v.w = fmaxf((hreg[3][jj] - mu[3]) * iv[3] * gg + bb, 0.f);
            *(float4*)&sHid[j * HSTRIDE + (mg << 2)] = v;
        }
    }
    __syncthreads();

    // ---- GEMM2: [128 x 128] @ [128 x 64]; thread tile 4m x 4j (2 jpairs) ----
    unsigned long long c2[4][2];
    #pragma unroll
    for (int a = 0; a < 4; a++) { c2[a][0] = 0ull; c2[a][1] = 0ull; }

    const float4* sW24 = (const float4*)sW2;
    #pragma unroll 8
    for (int k = 0; k < 128; k++) {
        float4 a = *(const float4*)&sHid[k * HSTRIDE + (mg << 2)];
        float4 w = sW24[(k << 4) + jg];
        unsigned long long pa0, pa1, pa2, pa3, q0, q1;
        PK(pa0, a.x, a.x); PK(pa1, a.y, a.y); PK(pa2, a.z, a.z); PK(pa3, a.w, a.w);
        PK(q0, w.x, w.y); PK(q1, w.z, w.w);
        FMA2(c2[0][0], pa0, q0, c2[0][0]); FMA2(c2[0][1], pa0, q1, c2[0][1]);
        FMA2(c2[1][0], pa1, q0, c2[1][0]); FMA2(c2[1][1], pa1, q1, c2[1][1]);
        FMA2(c2[2][0], pa2, q0, c2[2][0]); FMA2(c2[2][1], pa2, q1, c2[2][1]);
        FMA2(c2[3][0], pa3, q0, c2[3][0]); FMA2(c2[3][1], pa3, q1, c2[3][1]);
    }

    // epilogue: bias, residual, store
    {
        int j0 = jg << 2;
        float b0 = sb2[j0], bb1 = sb2[j0 + 1], bb2 = sb2[j0 + 2], bb3 = sb2[j0 + 3];
        #pragma unroll
        for (int mi = 0; mi < 4; mi++) {
            int n = blockIdx.x * TM + (mg << 2) + mi;
            if (n < N) {
                float o0, o1, o2, o3;
                UPK(o0, o1, c2[mi][0]);
                UPK(o2, o3, c2[mi][1]);
                o0 += b0; o1 += bb1; o2 += bb2; o3 += bb3;
                if (res) {
                    float4 r = *(const float4*)&res[n * H + j0];
                    o0 += r.x; o1 += r.y; o2 += r.z; o3 += r.w;
                }
                *(float4*)&out[n * H + j0] = make_float4(o0, o1, o2, o3);
            }
        }
    }
}

// ---------------- LN(64) + ReLU, warp per node ----------------
__global__ void k_ln64_relu(const float* __restrict__ in, float* __restrict__ out,
                            const float* __restrict__ g, const float* __restrict__ b, int N) {
    int warp = (blockIdx.x * blockDim.x + threadIdx.x) >> 5;
    int lane = threadIdx.x & 31;
    if (warp >= N) return;
    float v1 = in[warp * H + lane];
    float v2 = in[warp * H + lane + 32];
    float s = v1 + v2, q = v1 * v1 + v2 * v2;
    #pragma unroll
    for (int o = 16; o; o >>= 1) {
        s += __shfl_xor_sync(0xffffffffu, s, o);
        q += __shfl_xor_sync(0xffffffffu, q, o);
    }
    float mu = s * (1.f / 64.f);
    float var = q * (1.f / 64.f) - mu * mu;
    float inv = rsqrtf(var + 1e-5f);
    out[warp * H + lane]      = fmaxf((v1 - mu) * inv * g[lane] + b[lane], 0.f);
    out[warp * H + lane + 32] = fmaxf((v2 - mu) * inv * g[lane + 32] + b[lane + 32], 0.f);
}

// ---------------- final head ----------------
__global__ void k_final(const float* __restrict__ h, const float* __restrict__ g,
                        const float* __restrict__ b, const float* __restrict__ Wl,
                        const float* __restrict__ bl, float* __restrict__ out, int N) {
    int warp = (blockIdx.x * blockDim.x + threadIdx.x) >> 5;
    int lane = threadIdx.x & 31;
    if (warp >= N) return;
    float v1 = h[warp * H + lane];
    float v2 = h[warp * H + lane + 32];
    float s = v1 + v2, q = v1 * v1 + v2 * v2;
    #pragma unroll
    for (int o = 16; o; o >>= 1) {
        s += __shfl_xor_sync(0xffffffffu, s, o);
        q += __shfl_xor_sync(0xffffffffu, q, o);
    }
    float mu = s * (1.f / 64.f);
    float var = q * (1.f / 64.f) - mu * mu;
    float inv = rsqrtf(var + 1e-5f);
    float y1 = fmaxf((v1 - mu) * inv * g[lane] + b[lane], 0.f);
    float y2 = fmaxf((v2 - mu) * inv * g[lane + 32] + b[lane + 32], 0.f);
    float p = y1 * Wl[lane] + y2 * Wl[lane + 32];
    #pragma unroll
    for (int o = 16; o; o >>= 1) p += __shfl_xor_sync(0xffffffffu, p, o);
    if (lane == 0) {
        float logit = p + bl[0];
        out[warp]     = 1.f / (1.f + expf(-logit));
        out[N + warp] = logit;
    }
}

// ---------------- host launcher ----------------
extern "C" void kernel_launch(void* const* d_in, const int* in_sizes, int n_in,
                              void* d_out, int out_size) {
    const float* x      = (const float*)d_in[0];
    const int*   eidx   = (const int*)d_in[1];
    const float* W_enc  = (const float*)d_in[2];
    const float* b_enc  = (const float*)d_in[3];
    const float* t1     = (const float*)d_in[4];
    const float* W1a    = (const float*)d_in[5];
    const float* b1a    = (const float*)d_in[6];
    const float* g1a    = (const float*)d_in[7];
    const float* be1a   = (const float*)d_in[8];
    const float* W1b    = (const float*)d_in[9];
    const float* b1b    = (const float*)d_in[10];
    const float* g_n1   = (const float*)d_in[11];
    const float* b_n1   = (const float*)d_in[12];
    const float* t2     = (const float*)d_in[13];
    const float* W2a    = (const float*)d_in[14];
    const float* b2a    = (const float*)d_in[15];
    const float* g2a    = (const float*)d_in[16];
    const float* be2a   = (const float*)d_in[17];
    const float* W2b    = (const float*)d_in[18];
    const float* b2b    = (const float*)d_in[19];
    const float* g_n0   = (const float*)d_in[20];
    const float* b_n0   = (const float*)d_in[21];
    const float* W_lin  = (const float*)d_in[22];
    const float* b_lin  = (const float*)d_in[23];
    float* out = (float*)d_out;

    int N = in_sizes[0] / 16;
    int E = in_sizes[1] / 2;
    if (N > MAXN) N = MAXN;
    if (E > MAXE) E = MAXE;
    const int* src = eidx;
    const int* dst = eidx + E;

    float *pA, *pB, *pC, *pD, *pE;
    int *pOff, *pCur, *pAdj, *pBsum;
    cudaGetSymbolAddress((void**)&pA, d_bufA);
    cudaGetSymbolAddress((void**)&pB, d_bufB);
    cudaGetSymbolAddress((void**)&pC, d_bufC);
    cudaGetSymbolAddress((void**)&pD, d_bufD);
    cudaGetSymbolAddress((void**)&pE, d_bufE);
    cudaGetSymbolAddress((void**)&pOff, d_off);
    cudaGetSymbolAddress((void**)&pCur, d_cur);
    cudaGetSymbolAddress((void**)&pAdj, d_adj);
    cudaGetSymbolAddress((void**)&pBsum, d_bsum);

    static bool attr_done = false;
    const int mlp_smem = (8192 * 3 + 128 * HSTRIDE + 2048 * 2 + 128 * 2 + 128 * 3 + 64)
                         * (int)sizeof(float);
    if (!attr_done) {
        cudaFuncSetAttribute(k_mlp, cudaFuncAttributeMaxDynamicSharedMemorySize, mlp_smem);
        attr_done = true;
    }

    int nb_scan = (N + 1023) / 1024;
    int mlp_grid = (N + TM - 1) / TM;

    // encoder -> h0 (bufE)
    k_encoder<<<(N * H + 255) / 256, 256>>>(x, W_enc, b_enc, pE, N);

    // CSR build
    k_zero_int<<<(N + 255) / 256, 256>>>(pOff, N);
    k_count<<<(E + 255) / 256, 256>>>(dst, pOff, E);
    k_scan1<<<nb_scan, 1024>>>(pOff, pBsum, N);
    k_scan2<<<1, 32>>>(pBsum, nb_scan);
    k_scan3<<<nb_scan, 1024>>>(pOff, pCur, pBsum, N, E);
    k_scatter<<<(E + 255) / 256, 256>>>(src, dst, pCur, pAdj, E);

    // layer 1
    k_agg<<<(N + 3) / 4, 256>>>(pE, pA, pOff, pAdj, t1, N);
    k_mlp<<<mlp_grid, 512, mlp_smem>>>(pA, pB, (const float*)nullptr,
                                       W1a, b1a, g1a, be1a, W1b, b1b, N);

    // layer 2
    k_ln64_relu<<<(N + 7) / 8, 256>>>(pB, pC, g_n1, b_n1, N);
    k_agg<<<(N + 3) / 4, 256>>>(pC, pA, pOff, pAdj, t2, N);
    k_mlp<<<mlp_grid, 512, mlp_smem>>>(pA, pD, pB,
                                       W2a, b2a, g2a, be2a, W2b, b2b, N);

    // final head
    k_final<<<(N + 7) / 8, 256>>>(pD, g_n0, b_n0, W_lin, b_lin, out, N);
}

// round 3
// speedup vs baseline: 2.5707x; 1.1497x over previous
#include <cuda_runtime.h>
#include <cuda_bf16.h>
#include <math.h>

#define MAXN 100000
#define MAXE 1600000
#define H 64
#define H2 128

// ---------------- scratch (static device globals; no allocs) ----------------
__device__ float d_bufA[MAXN * H];   // agg output (both layers)
__device__ float d_bufB[MAXN * H];   // h1
__device__ float d_bufC[MAXN * H];   // g = relu(ln(h1))
__device__ float d_bufE[MAXN * H];   // h0
__device__ int   d_off[MAXN + 1];
__device__ int   d_cur[MAXN];
__device__ int   d_adj[MAXE];
__device__ int   d_bsum[1024];

// packed fp32x2 helpers (sm_103a FFMA2 path)
#define PK(d, lo, hi)  asm("mov.b64 %0, {%1, %2};" : "=l"(d) : "f"(lo), "f"(hi))
#define UPK(lo, hi, s) asm("mov.b64 {%0, %1}, %2;" : "=f"(lo), "=f"(hi) : "l"(s))
#define FMA2(d, a, b, c) asm("fma.rn.f32x2 %0, %1, %2, %3;" : "=l"(d) : "l"(a), "l"(b), "l"(c))

// ---------------- encoder: h = x @ W_enc + b_enc (float4 everywhere) --------
__global__ void k_encoder(const float* __restrict__ x, const float* __restrict__ W,
                          const float* __restrict__ b, float* __restrict__ h, int N) {
    __shared__ float4 sW[16 * 16];   // [k][q]  (q = output/4)
    __shared__ float4 sB[16];
    int tid = threadIdx.x;
    if (tid < 256) sW[tid] = ((const float4*)W)[tid];
    if (tid < 16)  sB[tid] = ((const float4*)b)[tid];
    __syncthreads();
    int idx = blockIdx.x * blockDim.x + threadIdx.x;   // one per (node, q)
    int total = N * 16;
    if (idx >= total) return;
    int n = idx >> 4, q = idx & 15;
    const float4* xr = (const float4*)(x + n * 16);
    float4 x0 = xr[0], x1 = xr[1], x2 = xr[2], x3 = xr[3];
    float4 acc = sB[q];
    #define ESTEP(xv, kk) { float4 w = sW[(kk) * 16 + q]; \
        acc.x += (xv) * w.x; acc.y += (xv) * w.y; acc.z += (xv) * w.z; acc.w += (xv) * w.w; }
    ESTEP(x0.x, 0)  ESTEP(x0.y, 1)  ESTEP(x0.z, 2)  ESTEP(x0.w, 3)
    ESTEP(x1.x, 4)  ESTEP(x1.y, 5)  ESTEP(x1.z, 6)  ESTEP(x1.w, 7)
    ESTEP(x2.x, 8)  ESTEP(x2.y, 9)  ESTEP(x2.z, 10) ESTEP(x2.w, 11)
    ESTEP(x3.x, 12) ESTEP(x3.y, 13) ESTEP(x3.z, 14) ESTEP(x3.w, 15)
    #undef ESTEP
    ((float4*)h)[idx] = acc;
}

// ---------------- CSR build ----------------
__global__ void k_zero_int(int* __restrict__ a, int n) {
    for (int i = blockIdx.x * blockDim.x + threadIdx.x; i < n; i += gridDim.x * blockDim.x)
        a[i] = 0;
}

__global__ void k_count(const int* __restrict__ dst, int* __restrict__ deg, int E) {
    for (int e = blockIdx.x * blockDim.x + threadIdx.x; e < E; e += gridDim.x * blockDim.x)
        atomicAdd(&deg[dst[e]], 1);
}

__global__ void k_scan1(int* __restrict__ data, int* __restrict__ bsum, int N) {
    __shared__ int s[1024];
    int i = blockIdx.x * 1024 + threadIdx.x;
    int v = (i < N) ? data[i] : 0;
    s[threadIdx.x] = v;
    __syncthreads();
    for (int off = 1; off < 1024; off <<= 1) {
        int t = (threadIdx.x >= off) ? s[threadIdx.x - off] : 0;
        __syncthreads();
        s[threadIdx.x] += t;
        __syncthreads();
    }
    if (i < N) data[i] = s[threadIdx.x] - v;   // exclusive
    if (threadIdx.x == 1023) bsum[blockIdx.x] = s[1023];
}

__global__ void k_scan2(int* __restrict__ bsum, int nb) {
    if (blockIdx.x == 0 && threadIdx.x == 0) {
        int run = 0;
        for (int b = 0; b < nb; b++) { int t = bsum[b]; bsum[b] = run; run += t; }
    }
}

__global__ void k_scan3(int* __restrict__ off, int* __restrict__ cur,
                        const int* __restrict__ bsum, int N, int E) {
    int i = blockIdx.x * blockDim.x + threadIdx.x;
    if (i < N) {
        int o = off[i] + bsum[i >> 10];
        off[i] = o;
        cur[i] = o;
    }
    if (i == 0) off[N] = E;
}

__global__ void k_scatter(const int* __restrict__ src, const int* __restrict__ dst,
                          int* __restrict__ cur, int* __restrict__ adj, int E) {
    for (int e = blockIdx.x * blockDim.x + threadIdx.x; e < E; e += gridDim.x * blockDim.x) {
        int p = atomicAdd(&cur[dst[e]], 1);
        adj[p] = src[e];
    }
}

// ---------------- GENConv softmax aggregation (max-free, CSR, float4) -------
// 16 threads per node, each handles 4 features; 4-edge unroll = 4 gather chains.
__device__ __forceinline__ void agg_acc(float4& num, float4& den, float4 v, float t) {
    v.x = fmaxf(v.x, 0.f) + 1e-7f;
    v.y = fmaxf(v.y, 0.f) + 1e-7f;
    v.z = fmaxf(v.z, 0.f) + 1e-7f;
    v.w = fmaxf(v.w, 0.f) + 1e-7f;
    float wx = __expf(v.x * t), wy = __expf(v.y * t);
    float wz = __expf(v.z * t), ww = __expf(v.w * t);
    num.x += v.x * wx; num.y += v.y * wy; num.z += v.z * wz; num.w += v.w * ww;
    den.x += wx; den.y += wy; den.z += wz; den.w += ww;
}

__global__ void __launch_bounds__(256)
k_agg(const float4* __restrict__ feat4, float4* __restrict__ out4,
      const int* __restrict__ off, const int* __restrict__ adj,
      const float* __restrict__ tptr, int N) {
    int gid = (blockIdx.x * 256 + threadIdx.x) >> 4;
    if (gid >= N) return;
    int f = threadIdx.x & 15;
    float t = __ldg(tptr);
    int beg = off[gid], end = off[gid + 1];
    float4 z = make_float4(0.f, 0.f, 0.f, 0.f);
    float4 n0 = z, n1 = z, n2 = z, n3 = z;
    float4 d0 = z, d1 = z, d2 = z, d3 = z;
    int j = beg;
    for (; j + 3 < end; j += 4) {
        int s0 = adj[j], s1 = adj[j + 1], s2 = adj[j + 2], s3 = adj[j + 3];
        float4 v0 = feat4[s0 * 16 + f];
        float4 v1 = feat4[s1 * 16 + f];
        float4 v2 = feat4[s2 * 16 + f];
        float4 v3 = feat4[s3 * 16 + f];
        agg_acc(n0, d0, v0, t);
        agg_acc(n1, d1, v1, t);
        agg_acc(n2, d2, v2, t);
        agg_acc(n3, d3, v3, t);
    }
    for (; j < end; j++) {
        int s = adj[j];
        agg_acc(n0, d0, feat4[s * 16 + f], t);
    }
    float4 self = feat4[gid * 16 + f];
    float4 num, den, o;
    num.x = (n0.x + n1.x) + (n2.x + n3.x);  den.x = (d0.x + d1.x) + (d2.x + d3.x);
    num.y = (n0.y + n1.y) + (n2.y + n3.y);  den.y = (d0.y + d1.y) + (d2.y + d3.y);
    num.z = (n0.z + n1.z) + (n2.z + n3.z);  den.z = (d0.z + d1.z) + (d2.z + d3.z);
    num.w = (n0.w + n1.w) + (n2.w + n3.w);  den.w = (d0.w + d1.w) + (d2.w + d3.w);
    o.x = num.x / (den.x + 1e-16f) + self.x;
    o.y = num.y / (den.y + 1e-16f) + self.y;
    o.z = num.z / (den.z + 1e-16f) + self.z;
    o.w = num.w / (den.w + 1e-16f) + self.w;
    out4[gid * 16 + f] = o;
}

// ---------------- fused MLP: relu(LN(in@W1+b1)) @ W2 + b2 + fused epilogue --
// MODE 0: out=h1, out2=relu(LN64(h1; gx,bx))            (layer-1 MLP + pre-norm of layer 2)
// MODE 1: h2 = gemm + res; final head:
//         y=relu(LN64(h2; gx,bx)); logit=y.Wl+bl; out[n]=sigmoid, out[N+n]=logit
#define TM 128
#define HSTRIDE 132
template <int MODE>
__global__ void __launch_bounds__(512, 1)
k_mlp(const float* __restrict__ in, float* __restrict__ out, float* __restrict__ out2,
      const float* __restrict__ res,
      const float* __restrict__ W1, const float* __restrict__ b1,
      const float* __restrict__ g1, const float* __restrict__ be1,
      const float* __restrict__ W2, const float* __restrict__ b2,
      const float* __restrict__ gx, const float* __restrict__ bx,
      const float* __restrict__ Wl, const float* __restrict__ bl, int N) {
    extern __shared__ float sm[];
    float* sW1  = sm;                       // 8192
    float* sW2  = sW1 + 8192;               // 8192
    float* sIn  = sW2 + 8192;               // 8192 (transposed [k][m])
    float* sHid = sIn + 8192;               // 128 x 132
    float* sRs  = sHid + 128 * HSTRIDE;     // 16 x 128
    float* sRq  = sRs + 2048;               // 16 x 128
    float* sMu  = sRq + 2048;               // 128
    float* sInv = sMu + 128;                // 128
    float* sb1  = sInv + 128;               // 128
    float* sg1  = sb1 + 128;                // 128
    float* sbe1 = sg1 + 128;                // 128
    float* sb2  = sbe1 + 128;               // 64
    float* sgx  = sb2 + 64;                 // 64
    float* sbx  = sgx + 64;                 // 64
    float* sWl  = sbx + 64;                 // 64

    const int tid = threadIdx.x;
    const int mg  = tid & 31;    // 32 m-groups x 4 nodes
    const int jg  = tid >> 5;    // 16 j-groups

    // load weights/biases
    {
        const float4* W14 = (const float4*)W1;
        const float4* W24 = (const float4*)W2;
        float4* sW14 = (float4*)sW1;
        float4* sW24 = (float4*)sW2;
        #pragma unroll
        for (int i = 0; i < 4; i++) {
            sW14[tid + i * 512] = W14[tid + i * 512];
            sW24[tid + i * 512] = W24[tid + i * 512];
        }
        if (tid < 128) { sb1[tid] = b1[tid]; sg1[tid] = g1[tid]; sbe1[tid] = be1[tid]; }
        else if (tid < 192) sb2[tid - 128] = b2[tid - 128];
        else if (tid < 256) sgx[tid - 192] = gx[tid - 192];
        else if (tid < 320) sbx[tid - 256] = bx[tid - 256];
        else if (MODE == 1 && tid < 384) sWl[tid - 320] = Wl[tid - 320];
    }

    // load + transpose input tile: sIn[k][m]
    {
        int nl = tid & 127;
        int q  = tid >> 7;       // 0..3
        int n  = blockIdx.x * TM + nl;
        if (n >= N) n = N - 1;
        const float4* ip = (const float4*)(in + n * H);
        #pragma unroll
        for (int i = 0; i < 4; i++) {
            float4 v = ip[q * 4 + i];
            int k0 = (q * 4 + i) * 4;
            sIn[(k0 + 0) * TM + nl] = v.x;
            sIn[(k0 + 1) * TM + nl] = v.y;
            sIn[(k0 + 2) * TM + nl] = v.z;
            sIn[(k0 + 3) * TM + nl] = v.w;
        }
    }
    __syncthreads();

    // ---- GEMM1: [128 x 64] @ [64 x 128]; thread tile 4m x 8j ----
    unsigned long long acc[4][4];
    #pragma unroll
    for (int a = 0; a < 4; a++)
        #pragma unroll
        for (int bq = 0; bq < 4; bq++) acc[a][bq] = 0ull;

    const float4* sIn4 = (const float4*)sIn;
    const float4* sW14 = (const float4*)sW1;
    #pragma unroll 8
    for (int k = 0; k < 64; k++) {
        float4 a  = sIn4[k * 32 + mg];
        float4 w0 = sW14[k * 32 + (jg << 1)];
        float4 w1 = sW14[k * 32 + (jg << 1) + 1];
        unsigned long long pa0, pa1, pa2, pa3, q0, q1, q2, q3;
        PK(pa0, a.x, a.x); PK(pa1, a.y, a.y); PK(pa2, a.z, a.z); PK(pa3, a.w, a.w);
        PK(q0, w0.x, w0.y); PK(q1, w0.z, w0.w); PK(q2, w1.x, w1.y); PK(q3, w1.z, w1.w);
        FMA2(acc[0][0], pa0, q0, acc[0][0]); FMA2(acc[0][1], pa0, q1, acc[0][1]);
        FMA2(acc[0][2], pa0, q2, acc[0][2]); FMA2(acc[0][3], pa0, q3, acc[0][3]);
        FMA2(acc[1][0], pa1, q0, acc[1][0]); FMA2(acc[1][1], pa1, q1, acc[1][1]);
        FMA2(acc[1][2], pa1, q2, acc[1][2]); FMA2(acc[1][3], pa1, q3, acc[1][3]);
        FMA2(acc[2][0], pa2, q0, acc[2][0]); FMA2(acc[2][1], pa2, q1, acc[2][1]);
        FMA2(acc[2][2], pa2, q2, acc[2][2]); FMA2(acc[2][3], pa2, q3, acc[2][3]);
        FMA2(acc[3][0], pa3, q0, acc[3][0]); FMA2(acc[3][1], pa3, q1, acc[3][1]);
        FMA2(acc[3][2], pa3, q2, acc[3][2]); FMA2(acc[3][3], pa3, q3, acc[3][3]);
    }

    // bias + per-node partial LN sums (over 128 hidden)
    float hreg[4][8];
    {
        float4 psum, psq;
        float* ps = (float*)&psum;
        float* pq = (float*)&psq;
        #pragma unroll
        for (int mi = 0; mi < 4; mi++) {
            float s = 0.f, q = 0.f;
            #pragma unroll
            for (int jp = 0; jp < 4; jp++) {
                float lo, hi;
                UPK(lo, hi, acc[mi][jp]);
                lo += sb1[(jg << 3) + 2 * jp];
                hi += sb1[(jg << 3) + 2 * jp + 1];
                hreg[mi][2 * jp] = lo; hreg[mi][2 * jp + 1] = hi;
                s += lo + hi; q += lo * lo + hi * hi;
            }
            ps[mi] = s; pq[mi] = q;
        }
        *(float4*)&sRs[jg * TM + (mg << 2)] = psum;
        *(float4*)&sRq[jg * TM + (mg << 2)] = psq;
    }
    __syncthreads();
    if (tid < TM) {
        float s = 0.f, q = 0.f;
        #pragma unroll
        for (int g = 0; g < 16; g++) { s += sRs[g * TM + tid]; q += sRq[g * TM + tid]; }
        float mu = s * (1.f / 128.f);
        float var = q * (1.f / 128.f) - mu * mu;
        sMu[tid] = mu;
        sInv[tid] = rsqrtf(var + 1e-5f);
    }
    __syncthreads();

    // LN + ReLU -> sHid[j][m]
    {
        float mu[4], iv[4];
        #pragma unroll
        for (int mi = 0; mi < 4; mi++) { mu[mi] = sMu[(mg << 2) + mi]; iv[mi] = sInv[(mg << 2) + mi]; }
        #pragma unroll
        for (int jj = 0; jj < 8; jj++) {
            int j = (jg << 3) + jj;
            float gg = sg1[j], bb = sbe1[j];
            float4 v;
            v.x = fmaxf((hreg[0][jj] - mu[0]) * iv[0] * gg + bb, 0.f);
            v.y = fmaxf((hreg[1][jj] - mu[1]) * iv[1] * gg + bb, 0.f);
            v.z = fmaxf((hreg[2][jj] - mu[2]) * iv[2] * gg + bb, 0.f);
            v.w = fmaxf((hreg[3][jj] - mu[3]) * iv[3] * gg + bb, 0.f);
            *(float4*)&sHid[j * HSTRIDE + (mg << 2)] = v;
        }
    }
    __syncthreads();

    // ---- GEMM2: [128 x 128] @ [128 x 64]; thread tile 4m x 4j ----
    unsigned long long c2[4][2];
    #pragma unroll
    for (int a = 0; a < 4; a++) { c2[a][0] = 0ull; c2[a][1] = 0ull; }

    const float4* sW24 = (const float4*)sW2;
    #pragma unroll 8
    for (int k = 0; k < 128; k++) {
        float4 a = *(const float4*)&sHid[k * HSTRIDE + (mg << 2)];
        float4 w = sW24[(k << 4) + jg];
        unsigned long long pa0, pa1, pa2, pa3, q0, q1;
        PK(pa0, a.x, a.x); PK(pa1, a.y, a.y); PK(pa2, a.z, a.z); PK(pa3, a.w, a.w);
        PK(q0, w.x, w.y); PK(q1, w.z, w.w);
        FMA2(c2[0][0], pa0, q0, c2[0][0]); FMA2(c2[0][1], pa0, q1, c2[0][1]);
        FMA2(c2[1][0], pa1, q0, c2[1][0]); FMA2(c2[1][1], pa1, q1, c2[1][1]);
        FMA2(c2[2][0], pa2, q0, c2[2][0]); FMA2(c2[2][1], pa2, q1, c2[2][1]);
        FMA2(c2[3][0], pa3, q0, c2[3][0]); FMA2(c2[3][1], pa3, q1, c2[3][1]);
    }

    // ---- fused epilogue ----
    const int j0 = jg << 2;
    float o[4][4];
    {
        float b0 = sb2[j0], bb1 = sb2[j0 + 1], bb2 = sb2[j0 + 2], bb3 = sb2[j0 + 3];
        float4 psum, psq;
        float* ps = (float*)&psum;
        float* pq = (float*)&psq;
        #pragma unroll
        for (int mi = 0; mi < 4; mi++) {
            int n = blockIdx.x * TM + (mg << 2) + mi;
            UPK(o[mi][0], o[mi][1], c2[mi][0]);
            UPK(o[mi][2], o[mi][3], c2[mi][1]);
            o[mi][0] += b0; o[mi][1] += bb1; o[mi][2] += bb2; o[mi][3] += bb3;
            if (MODE == 1) {
                int nc = (n < N) ? n : (N - 1);
                float4 r = *(const float4*)&res[nc * H + j0];
                o[mi][0] += r.x; o[mi][1] += r.y; o[mi][2] += r.z; o[mi][3] += r.w;
            } else {
                if (n < N)
                    *(float4*)&out[n * H + j0] = make_float4(o[mi][0], o[mi][1], o[mi][2], o[mi][3]);
            }
            float s = (o[mi][0] + o[mi][1]) + (o[mi][2] + o[mi][3]);
            float q = (o[mi][0] * o[mi][0] + o[mi][1] * o[mi][1])
                    + (o[mi][2] * o[mi][2] + o[mi][3] * o[mi][3]);
            ps[mi] = s; pq[mi] = q;
        }
        *(float4*)&sRs[jg * TM + (mg << 2)] = psum;
        *(float4*)&sRq[jg * TM + (mg << 2)] = psq;
    }
    __syncthreads();
    if (tid < TM) {
        float s = 0.f, q = 0.f;
        #pragma unroll
        for (int g = 0; g < 16; g++) { s += sRs[g * TM + tid]; q += sRq[g * TM + tid]; }
        float mu = s * (1.f / 64.f);
        float var = q * (1.f / 64.f) - mu * mu;
        sMu[tid] = mu;
        sInv[tid] = rsqrtf(var + 1e-5f);
    }
    __syncthreads();

    if (MODE == 0) {
        // write relu(LN64(h1)) to out2
        float g0 = sgx[j0], g1v = sgx[j0 + 1], g2v = sgx[j0 + 2], g3v = sgx[j0 + 3];
        float x0 = sbx[j0], x1 = sbx[j0 + 1], x2 = sbx[j0 + 2], x3 = sbx[j0 + 3];
        #pragma unroll
        for (int mi = 0; mi < 4; mi++) {
            int n = blockIdx.x * TM + (mg << 2) + mi;
            if (n < N) {
                float mu = sMu[(mg << 2) + mi], iv = sInv[(mg << 2) + mi];
                float4 y;
                y.x = fmaxf((o[mi][0] - mu) * iv * g0 + x0, 0.f);
                y.y = fmaxf((o[mi][1] - mu) * iv * g1v + x1, 0.f);
                y.z = fmaxf((o[mi][2] - mu) * iv * g2v + x2, 0.f);
                y.w = fmaxf((o[mi][3] - mu) * iv * g3v + x3, 0.f);
                *(float4*)&out2[n * H + j0] = y;
            }
        }
    } else {
        // final head: partial dot of relu(LN64(h2)) with W_lin
        float g0 = sgx[j0], g1v = sgx[j0 + 1], g2v = sgx[j0 + 2], g3v = sgx[j0 + 3];
        float x0 = sbx[j0], x1 = sbx[j0 + 1], x2 = sbx[j0 + 2], x3 = sbx[j0 + 3];
        float w0 = sWl[j0], w1 = sWl[j0 + 1], w2 = sWl[j0 + 2], w3 = sWl[j0 + 3];
        float4 pdot;
        float* pd = (float*)&pdot;
        #pragma unroll
        for (int mi = 0; mi < 4; mi++) {
            float mu = sMu[(mg << 2) + mi], iv = sInv[(mg << 2) + mi];
            float y0 = fmaxf((o[mi][0] - mu) * iv * g0 + x0, 0.f);
            float y1 = fmaxf((o[mi][1] - mu) * iv * g1v + x1, 0.f);
            float y2 = fmaxf((o[mi][2] - mu) * iv * g2v + x2, 0.f);
            float y3 = fmaxf((o[mi][3] - mu) * iv * g3v + x3, 0.f);
            pd[mi] = (y0 * w0 + y1 * w1) + (y2 * w2 + y3 * w3);
        }
        *(float4*)&sRs[jg * TM + (mg << 2)] = pdot;
        __syncthreads();
        if (tid < TM) {
            int n = blockIdx.x * TM + tid;
            if (n < N) {
                float p = 0.f;
                #pragma unroll
                for (int g = 0; g < 16; g++) p += sRs[g * TM + tid];
                float logit = p + __ldg(bl);
                out[n]     = 1.f / (1.f + expf(-logit));
                out[N + n] = logit;
            }
        }
    }
}

// ---------------- host launcher ----------------
extern "C" void kernel_launch(void* const* d_in, const int* in_sizes, int n_in,
                              void* d_out, int out_size) {
    const float* x      = (const float*)d_in[0];
    const int*   eidx   = (const int*)d_in[1];
    const float* W_enc  = (const float*)d_in[2];
    const float* b_enc  = (const float*)d_in[3];
    const float* t1     = (const float*)d_in[4];
    const float* W1a    = (const float*)d_in[5];
    const float* b1a    = (const float*)d_in[6];
    const float* g1a    = (const float*)d_in[7];
    const float* be1a   = (const float*)d_in[8];
    const float* W1b    = (const float*)d_in[9];
    const float* b1b    = (const float*)d_in[10];
    const float* g_n1   = (const float*)d_in[11];
    const float* b_n1   = (const float*)d_in[12];
    const float* t2     = (const float*)d_in[13];
    const float* W2a    = (const float*)d_in[14];
    const float* b2a    = (const float*)d_in[15];
    const float* g2a    = (const float*)d_in[16];
    const float* be2a   = (const float*)d_in[17];
    const float* W2b    = (const float*)d_in[18];
    const float* b2b    = (const float*)d_in[19];
    const float* g_n0   = (const float*)d_in[20];
    const float* b_n0   = (const float*)d_in[21];
    const float* W_lin  = (const float*)d_in[22];
    const float* b_lin  = (const float*)d_in[23];
    float* out = (float*)d_out;

    int N = in_sizes[0] / 16;
    int E = in_sizes[1] / 2;
    if (N > MAXN) N = MAXN;
    if (E > MAXE) E = MAXE;
    const int* src = eidx;
    const int* dst = eidx + E;

    float *pA, *pB, *pC, *pE;
    int *pOff, *pCur, *pAdj, *pBsum;
    cudaGetSymbolAddress((void**)&pA, d_bufA);
    cudaGetSymbolAddress((void**)&pB, d_bufB);
    cudaGetSymbolAddress((void**)&pC, d_bufC);
    cudaGetSymbolAddress((void**)&pE, d_bufE);
    cudaGetSymbolAddress((void**)&pOff, d_off);
    cudaGetSymbolAddress((void**)&pCur, d_cur);
    cudaGetSymbolAddress((void**)&pAdj, d_adj);
    cudaGetSymbolAddress((void**)&pBsum, d_bsum);

    const int mlp_smem = (8192 * 3 + 128 * HSTRIDE + 2048 * 2 + 128 * 2 + 128 * 3
                          + 64 + 64 * 3) * (int)sizeof(float);
    cudaFuncSetAttribute(k_mlp<0>, cudaFuncAttributeMaxDynamicSharedMemorySize, mlp_smem);
    cudaFuncSetAttribute(k_mlp<1>, cudaFuncAttributeMaxDynamicSharedMemorySize, mlp_smem);

    int nb_scan = (N + 1023) / 1024;
    int mlp_grid = (N + TM - 1) / TM;

    // encoder -> h0 (bufE)
    k_encoder<<<(N * 16 + 255) / 256, 256>>>(x, W_enc, b_enc, pE, N);

    // CSR build
    k_zero_int<<<(N + 255) / 256, 256>>>(pOff, N);
    k_count<<<(E + 255) / 256, 256>>>(dst, pOff, E);
    k_scan1<<<nb_scan, 1024>>>(pOff, pBsum, N);
    k_scan2<<<1, 32>>>(pBsum, nb_scan);
    k_scan3<<<nb_scan, 1024>>>(pOff, pCur, pBsum, N, E);
    k_scatter<<<(E + 255) / 256, 256>>>(src, dst, pCur, pAdj, E);

    // layer 1: agg(h0) -> bufA ; MLP1 -> h1 (bufB) + relu(LN(h1)) (bufC)
    k_agg<<<(N * 16 + 255) / 256, 256>>>((const float4*)pE, (float4*)pA, pOff, pAdj, t1, N);
    k_mlp<0><<<mlp_grid, 512, mlp_smem>>>(pA, pB, pC, (const float*)nullptr,
                                          W1a, b1a, g1a, be1a, W1b, b1b,
                                          g_n1, b_n1, (const float*)nullptr,
                                          (const float*)nullptr, N);

    // layer 2: agg(bufC) -> bufA ; MLP2 + res(h1) + final head -> out
    k_agg<<<(N * 16 + 255) / 256, 256>>>((const float4*)pC, (float4*)pA, pOff, pAdj, t2, N);
    k_mlp<1><<<mlp_grid, 512, mlp_smem>>>(pA, out, (float*)nullptr, pB,
                                          W2a, b2a, g2a, be2a, W2b, b2b,
                                          g_n0, b_n0, W_lin, b_lin, N);
}